// round 12
// baseline (speedup 1.0000x reference)
#include <cuda_runtime.h>
#include <cuda_fp16.h>
#include <cstdint>
#include <cstddef>

#define EPS 1e-8f
#define B_   16
#define CIN  128
#define COUT 128
#define HH   128
#define WW   128
#define SS   512
#define NTAP 9

// ---------------- scratch (__device__ globals; no allocs allowed) ----------
__device__ __half g_wA[(size_t)B_ * NTAP * COUT * CIN];   // [b][t][o][i]
__device__ __half g_xt[(size_t)B_ * HH * WW * CIN];       // [b][y][x][i] NHWC
__device__ unsigned g_arrive = 0, g_done = 0;             // reset at kernel end

// ---------------- helpers ---------------------------------------------------
__device__ __forceinline__ uint32_t smem_u32(const void* p) {
    uint32_t a;
    asm("{ .reg .u64 t; cvta.to.shared.u64 t, %1; cvt.u32.u64 %0, t; }" : "=r"(a) : "l"(p));
    return a;
}
#define CPA16(s, g) \
    asm volatile("cp.async.cg.shared.global [%0], [%1], 16;" :: "r"(s), "l"(g) : "memory")
#define CPA_COMMIT() asm volatile("cp.async.commit_group;" ::: "memory")
#define CPA_WAIT(n)  asm volatile("cp.async.wait_group %0;" :: "n"(n) : "memory")

__device__ __forceinline__ void ldsm_x4(uint32_t* r, uint32_t addr) {
    asm volatile("ldmatrix.sync.aligned.m8n8.x4.shared.b16 {%0,%1,%2,%3}, [%4];"
                 : "=r"(r[0]), "=r"(r[1]), "=r"(r[2]), "=r"(r[3]) : "r"(addr));
}
__device__ __forceinline__ void mma16816(float* c, const uint32_t* a, const uint32_t* b) {
    asm volatile(
        "mma.sync.aligned.m16n8k16.row.col.f32.f16.f16.f32 "
        "{%0,%1,%2,%3}, {%4,%5,%6,%7}, {%8,%9}, {%0,%1,%2,%3};"
        : "+f"(c[0]), "+f"(c[1]), "+f"(c[2]), "+f"(c[3])
        : "r"(a[0]), "r"(a[1]), "r"(a[2]), "r"(a[3]), "r"(b[0]), "r"(b[1]));
}

// ---------------- layout constants ------------------------------------------
#define SM_A     0
#define A_BYTES  32768
#define SM_X     (3 * A_BYTES)
#define XROWS    66
#define XPLANE   (XROWS * 256)
#define SM_TOTAL (SM_X + 6 * XPLANE)           // 98304 + 101376 = 199680
#define NUNITS   ((HH / 4) * 2 * B_)           // 1024
#define NGRID    148
#define TSTR     130

__device__ __forceinline__ uint32_t a_off(int buf, int r, int g) {
    return (uint32_t)(SM_A + buf * A_BYTES + r * 256 + ((g ^ (r & 7)) << 4));
}
__device__ __forceinline__ uint32_t x_off(int plane, int p, int g) {
    return (uint32_t)(SM_X + (plane * XROWS + p) * 256 + ((g ^ (p & 7)) << 4));
}

// issue cp.asyncs for one unit's X (6 planes) + A0 (G0), then A1 (G1)
__device__ __forceinline__ void stage_unit(const __half* __restrict__ xb,
                                           const __half* __restrict__ wb,
                                           int y, int x0, uint32_t sb, int tid) {
    for (int idx = tid; idx < 6 * XROWS * 16; idx += 256) {
        int plane = idx / (XROWS * 16);
        int rem = idx % (XROWS * 16);
        int p = rem >> 4, g = rem & 15;
        int yy = y - 1 + plane, gx = x0 + p - 1;
        uint32_t sa = sb + x_off(plane, p, g);
        if (yy >= 0 && yy < HH && gx >= 0 && gx < WW) {
            CPA16(sa, xb + ((size_t)yy * WW + gx) * CIN + g * 8);
        } else {
            asm volatile("st.shared.v4.b32 [%0], {%1,%1,%1,%1};" :: "r"(sa), "r"(0u) : "memory");
        }
    }
#pragma unroll
    for (int it = 0; it < 8; it++) {
        int idx = tid + it * 256;
        int r = idx >> 4, g = idx & 15;
        CPA16(sb + a_off(0, r, g), wb + (size_t)r * CIN + g * 8);
    }
    CPA_COMMIT();                                    // G0
#pragma unroll
    for (int it = 0; it < 8; it++) {
        int idx = tid + it * 256;
        int r = idx >> 4, g = idx & 15;
        CPA16(sb + a_off(1, r, g), wb + (size_t)(COUT * CIN) + (size_t)r * CIN + g * 8);
    }
    CPA_COMMIT();                                    // G1
}

// ---------------------------------------------------------------------------
// FUSED persistent kernel. 148 CTAs, 256 threads, 199680 B dynamic smem.
// Phase 1: grid-stride 4096 tasks: [0,2048) transpose NCHW->NHWC fp16,
//          [2048,4096) demod (with inline style modulation) -> g_wA.
//          Phase-1 scratch aliases the conv's dynamic smem.
// Global spin barrier (all 148 CTAs resident at 1 CTA/SM -> deadlock-free).
// Phase 2: persistent conv, grid-stride over 1024 units (identical to R11).
// ---------------------------------------------------------------------------
__global__ void __launch_bounds__(256, 1)
fused_kernel(const float* __restrict__ x, const float* __restrict__ weight,
             const float* __restrict__ style, const float* __restrict__ mod_w,
             const float* __restrict__ mod_b, float* __restrict__ out) {
    extern __shared__ __align__(1024) char smem[];
    uint32_t sb = smem_u32(smem);
    int tid = threadIdx.x, wid = tid >> 5, lane = tid & 31;

    // ======================= PHASE 1: prep =================================
    __half* T   = (__half*)smem;                     // 33280 B
    float* st   = (float*)(smem + 34816);            // 2048 B
    float* s_sm = (float*)(smem + 36864);            // 512 B
    float* red  = (float*)(smem + 37888);            // 1024 B

    for (int task = blockIdx.x; task < 4096; task += NGRID) {
        if (task < 2048) {
            // ---- transpose task: (b, y) ----
            int b = task >> 7, y = task & 127;
            const float* xb = x + ((size_t)b * CIN) * HH * WW + (size_t)y * WW;
            for (int idx = tid; idx < CIN * WW; idx += 256) {
                int i = idx >> 7, xx = idx & 127;
                T[xx * TSTR + i] = __float2half_rn(xb[(size_t)i * HH * WW + xx]);
            }
            __syncthreads();
            __half* dst = g_xt + (((size_t)b * HH + y) * WW) * CIN;
            for (int idx = tid; idx < WW * (CIN / 2); idx += 256) {
                int xx = idx >> 6, ip = idx & 63;
                uint32_t v = *(const uint32_t*)&T[xx * TSTR + 2 * ip];
                *(uint32_t*)&dst[(size_t)xx * CIN + 2 * ip] = v;
            }
        } else {
            // ---- demod task: (b, o), inline modstyle ----
            int tk = task - 2048;
            int b = tk >> 7, o = tk & 127;
            for (int j = tid; j < SS; j += 256) st[j] = style[(size_t)b * SS + j];
            __syncthreads();
            if (tid < CIN) {
                const float4* mw = (const float4*)(mod_w + (size_t)tid * SS);
                float a = 0.f;
#pragma unroll 4
                for (int j = 0; j < SS / 4; j++) {
                    float4 w4 = mw[j];
                    a += w4.x * st[4*j] + w4.y * st[4*j+1] + w4.z * st[4*j+2] + w4.w * st[4*j+3];
                }
                s_sm[tid] = a + mod_b[tid];
            }
            __syncthreads();

            const float* w = weight + (size_t)o * CIN * NTAP;   // w[o][i][t]
            float p = 0.f;
            for (int idx = tid; idx < CIN * NTAP; idx += 256) {
                int i = idx / NTAP, t = idx - i * NTAP;
                float v = w[i * NTAP + t] * s_sm[i];
                p += v * v;
            }
            red[tid] = p;
            __syncthreads();
            for (int off = 128; off > 0; off >>= 1) {
                if (tid < off) red[tid] += red[tid + off];
                __syncthreads();
            }
            float dec = rsqrtf(red[0] + EPS);
            if (tid < CIN) {
                int i = tid;
                float sv = s_sm[i] * dec;
#pragma unroll
                for (int t = 0; t < NTAP; t++)
                    g_wA[(((size_t)b * NTAP + t) * COUT + o) * CIN + i] =
                        __float2half_rn(w[i * NTAP + t] * sv);
            }
        }
        __syncthreads();   // retire smem scratch before next task
    }

    // ======================= GLOBAL BARRIER ================================
    __threadfence();
    if (tid == 0) {
        atomicAdd(&g_arrive, 1u);
        while (*((volatile unsigned*)&g_arrive) < NGRID) __nanosleep(64);
        __threadfence();
    }
    __syncthreads();

    // ======================= PHASE 2: persistent conv ======================
    int wo = (wid & 1) * 64;       // o base
    int wx = (wid >> 1) * 16;      // x base (0/16/32/48)

    int u = blockIdx.x;
    int b  = u >> 6;
    int rem = u & 63;
    int y  = (rem >> 1) * 4;
    int x0 = (rem & 1) * 64;
    const __half* wb = g_wA + ((size_t)b * NTAP) * COUT * CIN;
    const __half* xb = g_xt + ((size_t)b * HH) * WW * CIN;

    stage_unit(xb, wb, y, x0, sb, tid);   // first unit's G0, G1

    float acc[4][4][2][4];

    for (;;) {
#pragma unroll
        for (int yr = 0; yr < 4; yr++)
#pragma unroll
            for (int mt = 0; mt < 4; mt++)
#pragma unroll
                for (int nt = 0; nt < 2; nt++)
#pragma unroll
                    for (int q = 0; q < 4; q++) acc[yr][mt][nt][q] = 0.f;

        for (int t = 0; t < NTAP; t++) {
            CPA_WAIT(1);
            __syncthreads();            // one barrier per tap

            int buf = t % 3;
            int dy = t / 3, dx = t - 3 * dy;

            int ar_l = lane & 15, ac_g2 = (lane >> 4);
            int bnt = (lane >> 4) & 1, bg = (lane >> 3) & 1, br_l = lane & 7;

#pragma unroll
            for (int ks = 0; ks < 8; ks++) {
                uint32_t afr[4][4];
                uint32_t bfr[4][4];
#pragma unroll
                for (int mt = 0; mt < 4; mt++) {
                    int r = wo + mt * 16 + ar_l;
                    ldsm_x4(afr[mt], sb + a_off(buf, r, ks * 2 + ac_g2));
                }
#pragma unroll
                for (int yr = 0; yr < 4; yr++) {
                    int p = wx + bnt * 8 + br_l + dx;
                    ldsm_x4(bfr[yr], sb + x_off(dy + yr, p, ks * 2 + bg));
                }
#pragma unroll
                for (int yr = 0; yr < 4; yr++)
#pragma unroll
                    for (int mt = 0; mt < 4; mt++)
#pragma unroll
                        for (int nt = 0; nt < 2; nt++)
                            mma16816(acc[yr][mt][nt], afr[mt], &bfr[yr][nt * 2]);
            }
            // prefetch A for tap t+2 into buf (t+2)%3
            if (t + 2 < NTAP) {
                int pbuf = (t + 2) % 3;
                const __half* asrc = wb + (size_t)(t + 2) * COUT * CIN;
#pragma unroll
                for (int it = 0; it < 8; it++) {
                    int idx = tid + it * 256;
                    int r = idx >> 4, g = idx & 15;
                    CPA16(sb + a_off(pbuf, r, g), asrc + (size_t)r * CIN + g * 8);
                }
            }
            CPA_COMMIT();   // one group per tap (possibly empty)
        }

        __syncthreads();    // all warps done reading this unit's X/A smem

        // ---- issue NEXT unit's staging before this unit's epilogue ----
        int un = u + NGRID;
        bool more = (un < NUNITS);
        int nb = 0, ny = 0, nx0 = 0;
        const __half *nwb = wb, *nxb = xb;
        if (more) {
            nb  = un >> 6;
            int nrem = un & 63;
            ny  = (nrem >> 1) * 4;
            nx0 = (nrem & 1) * 64;
            nwb = g_wA + ((size_t)nb * NTAP) * COUT * CIN;
            nxb = g_xt + ((size_t)nb * HH) * WW * CIN;
            stage_unit(nxb, nwb, ny, nx0, sb, tid);   // flies under epilogue
        }

        // ---- epilogue: c frags -> out[b][o][y+yr][x0+x] ----
        int ml = lane >> 2, nl = (lane & 3) * 2;
#pragma unroll
        for (int yr = 0; yr < 4; yr++) {
            float* ob = out + ((size_t)b * COUT) * HH * WW + (size_t)(y + yr) * WW;
#pragma unroll
            for (int mt = 0; mt < 4; mt++) {
#pragma unroll
                for (int half = 0; half < 2; half++) {
                    int o = wo + mt * 16 + ml + half * 8;
                    float* orow = ob + (size_t)o * HH * WW;
#pragma unroll
                    for (int nt = 0; nt < 2; nt++) {
                        int xx = x0 + wx + nt * 8 + nl;
                        float2 v;
                        v.x = acc[yr][mt][nt][half * 2 + 0];
                        v.y = acc[yr][mt][nt][half * 2 + 1];
                        *(float2*)(orow + xx) = v;
                    }
                }
            }
        }

        if (!more) break;
        u = un; b = nb; y = ny; x0 = nx0; wb = nwb; xb = nxb;
    }

    // ======================= reset barrier counters ========================
    __syncthreads();
    if (tid == 0) {
        unsigned v = atomicAdd(&g_done, 1u);
        if (v == NGRID - 1u) {          // last CTA out resets for next replay
            g_arrive = 0u;
            g_done = 0u;
            __threadfence();
        }
    }
}

// ---------------------------------------------------------------------------
extern "C" void kernel_launch(void* const* d_in, const int* in_sizes, int n_in,
                              void* d_out, int out_size) {
    const float* x      = (const float*)d_in[0];
    const float* style  = (const float*)d_in[1];
    const float* weight = (const float*)d_in[2];
    const float* mod_w  = (const float*)d_in[3];
    const float* mod_b  = (const float*)d_in[4];
    float* out = (float*)d_out;

    cudaFuncSetAttribute(fused_kernel, cudaFuncAttributeMaxDynamicSharedMemorySize, SM_TOTAL);
    fused_kernel<<<NGRID, 256, SM_TOTAL>>>(x, weight, style, mod_w, mod_b, out);
}

// round 13
// speedup vs baseline: 1.0009x; 1.0009x over previous
#include <cuda_runtime.h>
#include <cuda_fp16.h>
#include <cstdint>
#include <cstddef>

#define EPS 1e-8f
#define B_   16
#define CIN  128
#define COUT 128
#define HH   128
#define WW   128
#define SS   512
#define NTAP 9

// ---------------- scratch (__device__ globals; no allocs allowed) ----------
__device__ __half g_wA[(size_t)B_ * NTAP * COUT * CIN];   // [b][t][o][i]
__device__ __half g_xt[(size_t)B_ * HH * WW * CIN];       // [b][y][x][i] NHWC
__device__ unsigned g_arrive = 0, g_done = 0;             // reset at kernel end

// ---------------- helpers ---------------------------------------------------
__device__ __forceinline__ uint32_t smem_u32(const void* p) {
    uint32_t a;
    asm("{ .reg .u64 t; cvta.to.shared.u64 t, %1; cvt.u32.u64 %0, t; }" : "=r"(a) : "l"(p));
    return a;
}
#define CPA16(s, g) \
    asm volatile("cp.async.cg.shared.global [%0], [%1], 16;" :: "r"(s), "l"(g) : "memory")
#define CPA_COMMIT() asm volatile("cp.async.commit_group;" ::: "memory")
#define CPA_WAIT(n)  asm volatile("cp.async.wait_group %0;" :: "n"(n) : "memory")

__device__ __forceinline__ void ldsm_x4(uint32_t* r, uint32_t addr) {
    asm volatile("ldmatrix.sync.aligned.m8n8.x4.shared.b16 {%0,%1,%2,%3}, [%4];"
                 : "=r"(r[0]), "=r"(r[1]), "=r"(r[2]), "=r"(r[3]) : "r"(addr));
}
__device__ __forceinline__ void mma16816(float* c, const uint32_t* a, const uint32_t* b) {
    asm volatile(
        "mma.sync.aligned.m16n8k16.row.col.f32.f16.f16.f32 "
        "{%0,%1,%2,%3}, {%4,%5,%6,%7}, {%8,%9}, {%0,%1,%2,%3};"
        : "+f"(c[0]), "+f"(c[1]), "+f"(c[2]), "+f"(c[3])
        : "r"(a[0]), "r"(a[1]), "r"(a[2]), "r"(a[3]), "r"(b[0]), "r"(b[1]));
}

// ---------------- layout constants ------------------------------------------
#define SM_A     0
#define A_BYTES  32768
#define SM_X     (3 * A_BYTES)
#define XROWS    66
#define XPLANE   (XROWS * 256)
#define SM_TOTAL (SM_X + 6 * XPLANE)           // 98304 + 101376 = 199680
#define NUNITS   ((HH / 4) * 2 * B_)           // 1024
#define NGRID    148
#define TSTR     130

__device__ __forceinline__ uint32_t a_off(int buf, int r, int g) {
    return (uint32_t)(SM_A + buf * A_BYTES + r * 256 + ((g ^ (r & 7)) << 4));
}
__device__ __forceinline__ uint32_t x_off(int plane, int p, int g) {
    return (uint32_t)(SM_X + (plane * XROWS + p) * 256 + ((g ^ (p & 7)) << 4));
}

// issue cp.asyncs for one unit's X (6 planes) + A0 (G0), then A1 (G1)
__device__ __forceinline__ void stage_unit(const __half* __restrict__ xb,
                                           const __half* __restrict__ wb,
                                           int y, int x0, uint32_t sb, int tid) {
    for (int idx = tid; idx < 6 * XROWS * 16; idx += 256) {
        int plane = idx / (XROWS * 16);
        int rem = idx % (XROWS * 16);
        int p = rem >> 4, g = rem & 15;
        int yy = y - 1 + plane, gx = x0 + p - 1;
        uint32_t sa = sb + x_off(plane, p, g);
        if (yy >= 0 && yy < HH && gx >= 0 && gx < WW) {
            CPA16(sa, xb + ((size_t)yy * WW + gx) * CIN + g * 8);
        } else {
            asm volatile("st.shared.v4.b32 [%0], {%1,%1,%1,%1};" :: "r"(sa), "r"(0u) : "memory");
        }
    }
#pragma unroll
    for (int it = 0; it < 8; it++) {
        int idx = tid + it * 256;
        int r = idx >> 4, g = idx & 15;
        CPA16(sb + a_off(0, r, g), wb + (size_t)r * CIN + g * 8);
    }
    CPA_COMMIT();                                    // G0
#pragma unroll
    for (int it = 0; it < 8; it++) {
        int idx = tid + it * 256;
        int r = idx >> 4, g = idx & 15;
        CPA16(sb + a_off(1, r, g), wb + (size_t)(COUT * CIN) + (size_t)r * CIN + g * 8);
    }
    CPA_COMMIT();                                    // G1
}

// ---------------------------------------------------------------------------
// FUSED persistent kernel. 148 CTAs, 256 threads, 199680 B dynamic smem.
// Phase 1: grid-stride 4096 tasks: [0,2048) transpose NCHW->NHWC fp16,
//          [2048,4096) demod (with inline style modulation) -> g_wA.
//          Phase-1 scratch aliases the conv's dynamic smem.
// Global spin barrier (all 148 CTAs resident at 1 CTA/SM -> deadlock-free).
// Phase 2: persistent conv, grid-stride over 1024 units (identical to R11).
// ---------------------------------------------------------------------------
__global__ void __launch_bounds__(256, 1)
fused_kernel(const float* __restrict__ x, const float* __restrict__ weight,
             const float* __restrict__ style, const float* __restrict__ mod_w,
             const float* __restrict__ mod_b, float* __restrict__ out) {
    extern __shared__ __align__(1024) char smem[];
    uint32_t sb = smem_u32(smem);
    int tid = threadIdx.x, wid = tid >> 5, lane = tid & 31;

    // ======================= PHASE 1: prep =================================
    __half* T   = (__half*)smem;                     // 33280 B
    float* st   = (float*)(smem + 34816);            // 2048 B
    float* s_sm = (float*)(smem + 36864);            // 512 B
    float* red  = (float*)(smem + 37888);            // 1024 B

    for (int task = blockIdx.x; task < 4096; task += NGRID) {
        if (task < 2048) {
            // ---- transpose task: (b, y) ----
            int b = task >> 7, y = task & 127;
            const float* xb = x + ((size_t)b * CIN) * HH * WW + (size_t)y * WW;
            for (int idx = tid; idx < CIN * WW; idx += 256) {
                int i = idx >> 7, xx = idx & 127;
                T[xx * TSTR + i] = __float2half_rn(xb[(size_t)i * HH * WW + xx]);
            }
            __syncthreads();
            __half* dst = g_xt + (((size_t)b * HH + y) * WW) * CIN;
            for (int idx = tid; idx < WW * (CIN / 2); idx += 256) {
                int xx = idx >> 6, ip = idx & 63;
                uint32_t v = *(const uint32_t*)&T[xx * TSTR + 2 * ip];
                *(uint32_t*)&dst[(size_t)xx * CIN + 2 * ip] = v;
            }
        } else {
            // ---- demod task: (b, o), inline modstyle ----
            int tk = task - 2048;
            int b = tk >> 7, o = tk & 127;
            for (int j = tid; j < SS; j += 256) st[j] = style[(size_t)b * SS + j];
            __syncthreads();
            if (tid < CIN) {
                const float4* mw = (const float4*)(mod_w + (size_t)tid * SS);
                float a = 0.f;
#pragma unroll 4
                for (int j = 0; j < SS / 4; j++) {
                    float4 w4 = mw[j];
                    a += w4.x * st[4*j] + w4.y * st[4*j+1] + w4.z * st[4*j+2] + w4.w * st[4*j+3];
                }
                s_sm[tid] = a + mod_b[tid];
            }
            __syncthreads();

            const float* w = weight + (size_t)o * CIN * NTAP;   // w[o][i][t]
            float p = 0.f;
            for (int idx = tid; idx < CIN * NTAP; idx += 256) {
                int i = idx / NTAP, t = idx - i * NTAP;
                float v = w[i * NTAP + t] * s_sm[i];
                p += v * v;
            }
            red[tid] = p;
            __syncthreads();
            for (int off = 128; off > 0; off >>= 1) {
                if (tid < off) red[tid] += red[tid + off];
                __syncthreads();
            }
            float dec = rsqrtf(red[0] + EPS);
            if (tid < CIN) {
                int i = tid;
                float sv = s_sm[i] * dec;
#pragma unroll
                for (int t = 0; t < NTAP; t++)
                    g_wA[(((size_t)b * NTAP + t) * COUT + o) * CIN + i] =
                        __float2half_rn(w[i * NTAP + t] * sv);
            }
        }
        __syncthreads();   // retire smem scratch before next task
    }

    // ======================= GLOBAL BARRIER ================================
    __threadfence();
    if (tid == 0) {
        atomicAdd(&g_arrive, 1u);
        while (*((volatile unsigned*)&g_arrive) < NGRID) __nanosleep(64);
        __threadfence();
    }
    __syncthreads();

    // ======================= PHASE 2: persistent conv ======================
    int wo = (wid & 1) * 64;       // o base
    int wx = (wid >> 1) * 16;      // x base (0/16/32/48)

    int u = blockIdx.x;
    int b  = u >> 6;
    int rem = u & 63;
    int y  = (rem >> 1) * 4;
    int x0 = (rem & 1) * 64;
    const __half* wb = g_wA + ((size_t)b * NTAP) * COUT * CIN;
    const __half* xb = g_xt + ((size_t)b * HH) * WW * CIN;

    stage_unit(xb, wb, y, x0, sb, tid);   // first unit's G0, G1

    float acc[4][4][2][4];

    for (;;) {
#pragma unroll
        for (int yr = 0; yr < 4; yr++)
#pragma unroll
            for (int mt = 0; mt < 4; mt++)
#pragma unroll
                for (int nt = 0; nt < 2; nt++)
#pragma unroll
                    for (int q = 0; q < 4; q++) acc[yr][mt][nt][q] = 0.f;

        for (int t = 0; t < NTAP; t++) {
            CPA_WAIT(1);
            __syncthreads();            // one barrier per tap

            int buf = t % 3;
            int dy = t / 3, dx = t - 3 * dy;

            int ar_l = lane & 15, ac_g2 = (lane >> 4);
            int bnt = (lane >> 4) & 1, bg = (lane >> 3) & 1, br_l = lane & 7;

#pragma unroll
            for (int ks = 0; ks < 8; ks++) {
                uint32_t afr[4][4];
                uint32_t bfr[4][4];
#pragma unroll
                for (int mt = 0; mt < 4; mt++) {
                    int r = wo + mt * 16 + ar_l;
                    ldsm_x4(afr[mt], sb + a_off(buf, r, ks * 2 + ac_g2));
                }
#pragma unroll
                for (int yr = 0; yr < 4; yr++) {
                    int p = wx + bnt * 8 + br_l + dx;
                    ldsm_x4(bfr[yr], sb + x_off(dy + yr, p, ks * 2 + bg));
                }
#pragma unroll
                for (int yr = 0; yr < 4; yr++)
#pragma unroll
                    for (int mt = 0; mt < 4; mt++)
#pragma unroll
                        for (int nt = 0; nt < 2; nt++)
                            mma16816(acc[yr][mt][nt], afr[mt], &bfr[yr][nt * 2]);
            }
            // prefetch A for tap t+2 into buf (t+2)%3
            if (t + 2 < NTAP) {
                int pbuf = (t + 2) % 3;
                const __half* asrc = wb + (size_t)(t + 2) * COUT * CIN;
#pragma unroll
                for (int it = 0; it < 8; it++) {
                    int idx = tid + it * 256;
                    int r = idx >> 4, g = idx & 15;
                    CPA16(sb + a_off(pbuf, r, g), asrc + (size_t)r * CIN + g * 8);
                }
            }
            CPA_COMMIT();   // one group per tap (possibly empty)
        }

        __syncthreads();    // all warps done reading this unit's X/A smem

        // ---- issue NEXT unit's staging before this unit's epilogue ----
        int un = u + NGRID;
        bool more = (un < NUNITS);
        int nb = 0, ny = 0, nx0 = 0;
        const __half *nwb = wb, *nxb = xb;
        if (more) {
            nb  = un >> 6;
            int nrem = un & 63;
            ny  = (nrem >> 1) * 4;
            nx0 = (nrem & 1) * 64;
            nwb = g_wA + ((size_t)nb * NTAP) * COUT * CIN;
            nxb = g_xt + ((size_t)nb * HH) * WW * CIN;
            stage_unit(nxb, nwb, ny, nx0, sb, tid);   // flies under epilogue
        }

        // ---- epilogue: c frags -> out[b][o][y+yr][x0+x] ----
        int ml = lane >> 2, nl = (lane & 3) * 2;
#pragma unroll
        for (int yr = 0; yr < 4; yr++) {
            float* ob = out + ((size_t)b * COUT) * HH * WW + (size_t)(y + yr) * WW;
#pragma unroll
            for (int mt = 0; mt < 4; mt++) {
#pragma unroll
                for (int half = 0; half < 2; half++) {
                    int o = wo + mt * 16 + ml + half * 8;
                    float* orow = ob + (size_t)o * HH * WW;
#pragma unroll
                    for (int nt = 0; nt < 2; nt++) {
                        int xx = x0 + wx + nt * 8 + nl;
                        float2 v;
                        v.x = acc[yr][mt][nt][half * 2 + 0];
                        v.y = acc[yr][mt][nt][half * 2 + 1];
                        *(float2*)(orow + xx) = v;
                    }
                }
            }
        }

        if (!more) break;
        u = un; b = nb; y = ny; x0 = nx0; wb = nwb; xb = nxb;
    }

    // ======================= reset barrier counters ========================
    __syncthreads();
    if (tid == 0) {
        unsigned v = atomicAdd(&g_done, 1u);
        if (v == NGRID - 1u) {          // last CTA out resets for next replay
            g_arrive = 0u;
            g_done = 0u;
            __threadfence();
        }
    }
}

// ---------------------------------------------------------------------------
extern "C" void kernel_launch(void* const* d_in, const int* in_sizes, int n_in,
                              void* d_out, int out_size) {
    const float* x      = (const float*)d_in[0];
    const float* style  = (const float*)d_in[1];
    const float* weight = (const float*)d_in[2];
    const float* mod_w  = (const float*)d_in[3];
    const float* mod_b  = (const float*)d_in[4];
    float* out = (float*)d_out;

    cudaFuncSetAttribute(fused_kernel, cudaFuncAttributeMaxDynamicSharedMemorySize, SM_TOTAL);
    fused_kernel<<<NGRID, 256, SM_TOTAL>>>(x, weight, style, mod_w, mod_b, out);
}

// round 14
// speedup vs baseline: 1.3863x; 1.3850x over previous
#include <cuda_runtime.h>
#include <cuda_fp16.h>
#include <cstdint>
#include <cstddef>

#define EPS 1e-8f
#define B_   16
#define CIN  128
#define COUT 128
#define HH   128
#define WW   128
#define SS   512
#define NTAP 9

// ---------------- scratch (__device__ globals; no allocs allowed) ----------
__device__ __half g_wA[(size_t)B_ * NTAP * COUT * CIN];   // [b][t][o][i]
__device__ __half g_xt[(size_t)B_ * HH * WW * CIN];       // [b][y][x][i] NHWC

// ---------------- helpers ---------------------------------------------------
__device__ __forceinline__ uint32_t smem_u32(const void* p) {
    uint32_t a;
    asm("{ .reg .u64 t; cvta.to.shared.u64 t, %1; cvt.u32.u64 %0, t; }" : "=r"(a) : "l"(p));
    return a;
}
#define CPA16(s, g) \
    asm volatile("cp.async.cg.shared.global [%0], [%1], 16;" :: "r"(s), "l"(g) : "memory")
#define CPA_COMMIT() asm volatile("cp.async.commit_group;" ::: "memory")
#define CPA_WAIT(n)  asm volatile("cp.async.wait_group %0;" :: "n"(n) : "memory")

__device__ __forceinline__ void ldsm_x4(uint32_t* r, uint32_t addr) {
    asm volatile("ldmatrix.sync.aligned.m8n8.x4.shared.b16 {%0,%1,%2,%3}, [%4];"
                 : "=r"(r[0]), "=r"(r[1]), "=r"(r[2]), "=r"(r[3]) : "r"(addr));
}
__device__ __forceinline__ void mma16816(float* c, const uint32_t* a, const uint32_t* b) {
    asm volatile(
        "mma.sync.aligned.m16n8k16.row.col.f32.f16.f16.f32 "
        "{%0,%1,%2,%3}, {%4,%5,%6,%7}, {%8,%9}, {%0,%1,%2,%3};"
        : "+f"(c[0]), "+f"(c[1]), "+f"(c[2]), "+f"(c[3])
        : "r"(a[0]), "r"(a[1]), "r"(a[2]), "r"(a[3]), "r"(b[0]), "r"(b[1]));
}

// ---------------------------------------------------------------------------
// Kernel 1 (FUSED prep): blocks [0,2048) transpose NCHW->NHWC fp16;
//   blocks [2048,4096) demod -> g_wA, with INLINE style modulation
//   (no separate modstyle kernel). High-occupancy launch (static smem only).
// ---------------------------------------------------------------------------
#define TSTR 130
__global__ void __launch_bounds__(256)
prep_kernel(const float* __restrict__ x, const float* __restrict__ weight,
            const float* __restrict__ style, const float* __restrict__ mod_w,
            const float* __restrict__ mod_b) {
    __shared__ __half T[WW * TSTR];     // transpose role only (33 KB)
    __shared__ float st[SS];
    __shared__ float s_sm[CIN];
    __shared__ float red[256];
    int tid = threadIdx.x;

    if (blockIdx.x < 2048) {
        // ---- transpose role: blk -> (b, y) ----
        int blk = blockIdx.x;
        int b = blk >> 7, y = blk & 127;
        const float* xb = x + ((size_t)b * CIN) * HH * WW + (size_t)y * WW;
        for (int idx = tid; idx < CIN * WW; idx += 256) {
            int i = idx >> 7, xx = idx & 127;
            T[xx * TSTR + i] = __float2half_rn(xb[(size_t)i * HH * WW + xx]);
        }
        __syncthreads();
        __half* dst = g_xt + (((size_t)b * HH + y) * WW) * CIN;
        for (int idx = tid; idx < WW * (CIN / 2); idx += 256) {
            int xx = idx >> 6, ip = idx & 63;
            uint32_t v = *(const uint32_t*)&T[xx * TSTR + 2 * ip];
            *(uint32_t*)&dst[(size_t)xx * CIN + 2 * ip] = v;
        }
    } else {
        // ---- demod role: blk -> (b, o), inline modstyle ----
        int blk = blockIdx.x - 2048;
        int b = blk >> 7, o = blk & 127;
        for (int j = tid; j < SS; j += 256) st[j] = style[(size_t)b * SS + j];
        __syncthreads();
        if (tid < CIN) {
            const float4* mw = (const float4*)(mod_w + (size_t)tid * SS);
            float a = 0.f;
#pragma unroll 4
            for (int j = 0; j < SS / 4; j++) {
                float4 w4 = mw[j];
                a += w4.x * st[4*j] + w4.y * st[4*j+1] + w4.z * st[4*j+2] + w4.w * st[4*j+3];
            }
            s_sm[tid] = a + mod_b[tid];
        }
        __syncthreads();

        const float* w = weight + (size_t)o * CIN * NTAP;   // w[o][i][t]
        float p = 0.f;
        for (int idx = tid; idx < CIN * NTAP; idx += 256) {
            int i = idx / NTAP, t = idx - i * NTAP;
            float v = w[i * NTAP + t] * s_sm[i];
            p += v * v;
        }
        red[tid] = p;
        __syncthreads();
        for (int off = 128; off > 0; off >>= 1) {
            if (tid < off) red[tid] += red[tid + off];
            __syncthreads();
        }
        float dec = rsqrtf(red[0] + EPS);

        if (tid < CIN) {
            int i = tid;
            float sv = s_sm[i] * dec;
#pragma unroll
            for (int t = 0; t < NTAP; t++)
                g_wA[(((size_t)b * NTAP + t) * COUT + o) * CIN + i] =
                    __float2half_rn(w[i * NTAP + t] * sv);
        }
    }
}

// ---------------------------------------------------------------------------
// Kernel 2: PERSISTENT mma.sync conv. grid = 148 CTAs, grid-stride over
// 1024 units (b, ygrp, xh). Per unit: o=128 x x=64 x 4 y-rows.
//   Per unit: G0 = {X planes 0..5, A0}, G1 = {A1}, one group per tap.
//   After a unit's mainloop, X smem is dead -> barrier, then issue the NEXT
//   unit's X+A0/A1 cp.asyncs, then run current epilogue (overlaps staging).
// smem = 3*32768 (A) + 6*66*256 (X) = 199680 B -> 1 CTA/SM.
// Warp tile 64(o) x 16(x) x 4 rows. Per k16: 4 ldsm_x4 A + 4 ldsm_x4 B -> 32 MMA.
// ---------------------------------------------------------------------------
#define SM_A     0
#define A_BYTES  32768
#define SM_X     (3 * A_BYTES)
#define XROWS    66
#define XPLANE   (XROWS * 256)
#define SM_TOTAL (SM_X + 6 * XPLANE)           // 98304 + 101376 = 199680
#define NUNITS   ((HH / 4) * 2 * B_)           // 1024
#define NGRID    148

__device__ __forceinline__ uint32_t a_off(int buf, int r, int g) {
    return (uint32_t)(SM_A + buf * A_BYTES + r * 256 + ((g ^ (r & 7)) << 4));
}
__device__ __forceinline__ uint32_t x_off(int plane, int p, int g) {
    return (uint32_t)(SM_X + (plane * XROWS + p) * 256 + ((g ^ (p & 7)) << 4));
}

// issue cp.asyncs for one unit's X (6 planes) + A0 (G0), then A1 (G1)
__device__ __forceinline__ void stage_unit(const __half* __restrict__ xb,
                                           const __half* __restrict__ wb,
                                           int y, int x0, uint32_t sb, int tid) {
    for (int idx = tid; idx < 6 * XROWS * 16; idx += 256) {
        int plane = idx / (XROWS * 16);
        int rem = idx % (XROWS * 16);
        int p = rem >> 4, g = rem & 15;
        int yy = y - 1 + plane, gx = x0 + p - 1;
        uint32_t sa = sb + x_off(plane, p, g);
        if (yy >= 0 && yy < HH && gx >= 0 && gx < WW) {
            CPA16(sa, xb + ((size_t)yy * WW + gx) * CIN + g * 8);
        } else {
            asm volatile("st.shared.v4.b32 [%0], {%1,%1,%1,%1};" :: "r"(sa), "r"(0u) : "memory");
        }
    }
#pragma unroll
    for (int it = 0; it < 8; it++) {
        int idx = tid + it * 256;
        int r = idx >> 4, g = idx & 15;
        CPA16(sb + a_off(0, r, g), wb + (size_t)r * CIN + g * 8);
    }
    CPA_COMMIT();                                    // G0
#pragma unroll
    for (int it = 0; it < 8; it++) {
        int idx = tid + it * 256;
        int r = idx >> 4, g = idx & 15;
        CPA16(sb + a_off(1, r, g), wb + (size_t)(COUT * CIN) + (size_t)r * CIN + g * 8);
    }
    CPA_COMMIT();                                    // G1
}

__global__ void __launch_bounds__(256, 1)
conv_mma_kernel(const __half* __restrict__ xt, float* __restrict__ out) {
    extern __shared__ __align__(1024) char smem[];
    uint32_t sb = smem_u32(smem);
    int tid = threadIdx.x, wid = tid >> 5, lane = tid & 31;
    int wo = (wid & 1) * 64;       // o base
    int wx = (wid >> 1) * 16;      // x base (0/16/32/48)

    int u = blockIdx.x;
    if (u >= NUNITS) return;

    // decode unit -> (b, y, x0)
    int b  = u >> 6;
    int rem = u & 63;
    int y  = (rem >> 1) * 4;
    int x0 = (rem & 1) * 64;
    const __half* wb = g_wA + ((size_t)b * NTAP) * COUT * CIN;
    const __half* xb = xt + ((size_t)b * HH) * WW * CIN;

    stage_unit(xb, wb, y, x0, sb, tid);   // first unit's G0, G1

    float acc[4][4][2][4];

    for (;;) {
#pragma unroll
        for (int yr = 0; yr < 4; yr++)
#pragma unroll
            for (int mt = 0; mt < 4; mt++)
#pragma unroll
                for (int nt = 0; nt < 2; nt++)
#pragma unroll
                    for (int q = 0; q < 4; q++) acc[yr][mt][nt][q] = 0.f;

        for (int t = 0; t < NTAP; t++) {
            CPA_WAIT(1);
            __syncthreads();            // one barrier per tap

            int buf = t % 3;
            int dy = t / 3, dx = t - 3 * dy;

            int ar_l = lane & 15, ac_g2 = (lane >> 4);
            int bnt = (lane >> 4) & 1, bg = (lane >> 3) & 1, br_l = lane & 7;

#pragma unroll
            for (int ks = 0; ks < 8; ks++) {
                uint32_t afr[4][4];
                uint32_t bfr[4][4];
#pragma unroll
                for (int mt = 0; mt < 4; mt++) {
                    int r = wo + mt * 16 + ar_l;
                    ldsm_x4(afr[mt], sb + a_off(buf, r, ks * 2 + ac_g2));
                }
#pragma unroll
                for (int yr = 0; yr < 4; yr++) {
                    int p = wx + bnt * 8 + br_l + dx;
                    ldsm_x4(bfr[yr], sb + x_off(dy + yr, p, ks * 2 + bg));
                }
#pragma unroll
                for (int yr = 0; yr < 4; yr++)
#pragma unroll
                    for (int mt = 0; mt < 4; mt++)
#pragma unroll
                        for (int nt = 0; nt < 2; nt++)
                            mma16816(acc[yr][mt][nt], afr[mt], &bfr[yr][nt * 2]);
            }
            // prefetch A for tap t+2 into buf (t+2)%3
            if (t + 2 < NTAP) {
                int pbuf = (t + 2) % 3;
                const __half* asrc = wb + (size_t)(t + 2) * COUT * CIN;
#pragma unroll
                for (int it = 0; it < 8; it++) {
                    int idx = tid + it * 256;
                    int r = idx >> 4, g = idx & 15;
                    CPA16(sb + a_off(pbuf, r, g), asrc + (size_t)r * CIN + g * 8);
                }
            }
            CPA_COMMIT();   // one group per tap (possibly empty)
        }

        __syncthreads();    // all warps done reading this unit's X/A smem

        // ---- issue NEXT unit's staging before this unit's epilogue ----
        int un = u + NGRID;
        bool more = (un < NUNITS);
        int nb = 0, ny = 0, nx0 = 0;
        const __half *nwb = wb, *nxb = xb;
        if (more) {
            nb  = un >> 6;
            int nrem = un & 63;
            ny  = (nrem >> 1) * 4;
            nx0 = (nrem & 1) * 64;
            nwb = g_wA + ((size_t)nb * NTAP) * COUT * CIN;
            nxb = xt + ((size_t)nb * HH) * WW * CIN;
            stage_unit(nxb, nwb, ny, nx0, sb, tid);   // flies under epilogue
        }

        // ---- epilogue: c frags -> out[b][o][y+yr][x0+x] ----
        int ml = lane >> 2, nl = (lane & 3) * 2;
#pragma unroll
        for (int yr = 0; yr < 4; yr++) {
            float* ob = out + ((size_t)b * COUT) * HH * WW + (size_t)(y + yr) * WW;
#pragma unroll
            for (int mt = 0; mt < 4; mt++) {
#pragma unroll
                for (int half = 0; half < 2; half++) {
                    int o = wo + mt * 16 + ml + half * 8;
                    float* orow = ob + (size_t)o * HH * WW;
#pragma unroll
                    for (int nt = 0; nt < 2; nt++) {
                        int xx = x0 + wx + nt * 8 + nl;
                        float2 v;
                        v.x = acc[yr][mt][nt][half * 2 + 0];
                        v.y = acc[yr][mt][nt][half * 2 + 1];
                        *(float2*)(orow + xx) = v;
                    }
                }
            }
        }

        if (!more) break;
        u = un; b = nb; y = ny; x0 = nx0; wb = nwb; xb = nxb;
    }
}

// ---------------------------------------------------------------------------
extern "C" void kernel_launch(void* const* d_in, const int* in_sizes, int n_in,
                              void* d_out, int out_size) {
    const float* x      = (const float*)d_in[0];
    const float* style  = (const float*)d_in[1];
    const float* weight = (const float*)d_in[2];
    const float* mod_w  = (const float*)d_in[3];
    const float* mod_b  = (const float*)d_in[4];
    float* out = (float*)d_out;

    prep_kernel<<<4096, 256>>>(x, weight, style, mod_w, mod_b);

    __half* xt_ptr = nullptr;
    cudaGetSymbolAddress((void**)&xt_ptr, g_xt);
    cudaFuncSetAttribute(conv_mma_kernel, cudaFuncAttributeMaxDynamicSharedMemorySize, SM_TOTAL);
    conv_mma_kernel<<<NGRID, 256, SM_TOTAL>>>(xt_ptr, out);
}

// round 15
// speedup vs baseline: 2.1383x; 1.5424x over previous
#include <cuda_runtime.h>
#include <cuda_fp16.h>
#include <cstdint>
#include <cstddef>

#define EPS 1e-8f
#define B_   16
#define CIN  128
#define COUT 128
#define HH   128
#define WW   128
#define SS   512
#define NTAP 9

// ---------------- scratch (__device__ globals; no allocs allowed) ----------
__device__ float  g_s[B_ * CIN];
__device__ __half g_wA[(size_t)B_ * NTAP * COUT * CIN];   // [b][t][o][i]
__device__ __half g_xt[(size_t)B_ * HH * WW * CIN];       // [b][y][x][i] NHWC

// ---------------- helpers ---------------------------------------------------
__device__ __forceinline__ uint32_t smem_u32(const void* p) {
    uint32_t a;
    asm("{ .reg .u64 t; cvta.to.shared.u64 t, %1; cvt.u32.u64 %0, t; }" : "=r"(a) : "l"(p));
    return a;
}
#define CPA16(s, g) \
    asm volatile("cp.async.cg.shared.global [%0], [%1], 16;" :: "r"(s), "l"(g) : "memory")
#define CPA_COMMIT() asm volatile("cp.async.commit_group;" ::: "memory")
#define CPA_WAIT(n)  asm volatile("cp.async.wait_group %0;" :: "n"(n) : "memory")

__device__ __forceinline__ void ldsm_x4(uint32_t* r, uint32_t addr) {
    asm volatile("ldmatrix.sync.aligned.m8n8.x4.shared.b16 {%0,%1,%2,%3}, [%4];"
                 : "=r"(r[0]), "=r"(r[1]), "=r"(r[2]), "=r"(r[3]) : "r"(addr));
}
__device__ __forceinline__ void mma16816(float* c, const uint32_t* a, const uint32_t* b) {
    asm volatile(
        "mma.sync.aligned.m16n8k16.row.col.f32.f16.f16.f32 "
        "{%0,%1,%2,%3}, {%4,%5,%6,%7}, {%8,%9}, {%0,%1,%2,%3};"
        : "+f"(c[0]), "+f"(c[1]), "+f"(c[2]), "+f"(c[3])
        : "r"(a[0]), "r"(a[1]), "r"(a[2]), "r"(a[3]), "r"(b[0]), "r"(b[1]));
}

// ---------------------------------------------------------------------------
// Kernel 1: s[b][i] = style[b] . mod_w[i] + mod_b[i]  (tiny, reads mod_w once)
// ---------------------------------------------------------------------------
__global__ void modstyle_kernel(const float* __restrict__ style,
                                const float* __restrict__ mod_w,
                                const float* __restrict__ mod_b) {
    int b = blockIdx.y;
    int w = threadIdx.x >> 5, lane = threadIdx.x & 31;
    int i = blockIdx.x * 4 + w;

    const float4* mw = (const float4*)(mod_w + (size_t)i * SS);
    const float4* st = (const float4*)(style + (size_t)b * SS);
    float acc = 0.f;
#pragma unroll
    for (int j = 0; j < 4; j++) {
        float4 a = mw[lane + j * 32];
        float4 s4 = st[lane + j * 32];
        acc += a.x * s4.x + a.y * s4.y + a.z * s4.z + a.w * s4.w;
    }
#pragma unroll
    for (int off = 16; off > 0; off >>= 1)
        acc += __shfl_xor_sync(0xFFFFFFFFu, acc, off);
    if (lane == 0) g_s[b * CIN + i] = acc + mod_b[i];
}

// ---------------------------------------------------------------------------
// Kernel 2 (FUSED): blocks [0,2048) transpose NCHW->NHWC fp16;
//                   blocks [2048,4096) demod (reads g_s) -> g_wA.
// ---------------------------------------------------------------------------
#define TSTR 130
__global__ void __launch_bounds__(256)
prep_kernel(const float* __restrict__ x, const float* __restrict__ weight) {
    __shared__ __half T[WW * TSTR];     // transpose role only (33 KB)
    __shared__ float s_sm[CIN];
    __shared__ float red[256];
    int tid = threadIdx.x;

    if (blockIdx.x < 2048) {
        // ---- transpose role: blk -> (b, y) ----
        int blk = blockIdx.x;
        int b = blk >> 7, y = blk & 127;
        const float* xb = x + ((size_t)b * CIN) * HH * WW + (size_t)y * WW;
        for (int idx = tid; idx < CIN * WW; idx += 256) {
            int i = idx >> 7, xx = idx & 127;
            T[xx * TSTR + i] = __float2half_rn(xb[(size_t)i * HH * WW + xx]);
        }
        __syncthreads();
        __half* dst = g_xt + (((size_t)b * HH + y) * WW) * CIN;
        for (int idx = tid; idx < WW * (CIN / 2); idx += 256) {
            int xx = idx >> 6, ip = idx & 63;
            uint32_t v = *(const uint32_t*)&T[xx * TSTR + 2 * ip];
            *(uint32_t*)&dst[(size_t)xx * CIN + 2 * ip] = v;
        }
    } else {
        // ---- demod role: blk -> (b, o) ----
        int blk = blockIdx.x - 2048;
        int b = blk >> 7, o = blk & 127;
        if (tid < CIN) s_sm[tid] = g_s[b * CIN + tid];
        __syncthreads();

        const float* w = weight + (size_t)o * CIN * NTAP;   // w[o][i][t]
        float p = 0.f;
        for (int idx = tid; idx < CIN * NTAP; idx += 256) {
            int i = idx / NTAP, t = idx - i * NTAP;
            float v = w[i * NTAP + t] * s_sm[i];
            p += v * v;
        }
        red[tid] = p;
        __syncthreads();
        for (int off = 128; off > 0; off >>= 1) {
            if (tid < off) red[tid] += red[tid + off];
            __syncthreads();
        }
        float dec = rsqrtf(red[0] + EPS);

        if (tid < CIN) {
            int i = tid;
            float sv = s_sm[i] * dec;
#pragma unroll
            for (int t = 0; t < NTAP; t++)
                g_wA[(((size_t)b * NTAP + t) * COUT + o) * CIN + i] =
                    __float2half_rn(w[i * NTAP + t] * sv);
        }
    }
}

// ---------------------------------------------------------------------------
// Kernel 3: PERSISTENT mma.sync conv (unchanged from the 180.2us measurement).
// grid = 148 CTAs, grid-stride over 1024 units (b, ygrp, xh).
// Per unit: o=128 x x=64 x 4 y-rows; G0={X planes 0..5, A0}, G1={A1},
// one commit group per tap; next unit's staging issued under the epilogue.
// smem = 3*32768 (A) + 6*66*256 (X) = 199680 B -> 1 CTA/SM.
// ---------------------------------------------------------------------------
#define SM_A     0
#define A_BYTES  32768
#define SM_X     (3 * A_BYTES)
#define XROWS    66
#define XPLANE   (XROWS * 256)
#define SM_TOTAL (SM_X + 6 * XPLANE)           // 98304 + 101376 = 199680
#define NUNITS   ((HH / 4) * 2 * B_)           // 1024
#define NGRID    148

__device__ __forceinline__ uint32_t a_off(int buf, int r, int g) {
    return (uint32_t)(SM_A + buf * A_BYTES + r * 256 + ((g ^ (r & 7)) << 4));
}
__device__ __forceinline__ uint32_t x_off(int plane, int p, int g) {
    return (uint32_t)(SM_X + (plane * XROWS + p) * 256 + ((g ^ (p & 7)) << 4));
}

// issue cp.asyncs for one unit's X (6 planes) + A0 (G0), then A1 (G1)
__device__ __forceinline__ void stage_unit(const __half* __restrict__ xb,
                                           const __half* __restrict__ wb,
                                           int y, int x0, uint32_t sb, int tid) {
    for (int idx = tid; idx < 6 * XROWS * 16; idx += 256) {
        int plane = idx / (XROWS * 16);
        int rem = idx % (XROWS * 16);
        int p = rem >> 4, g = rem & 15;
        int yy = y - 1 + plane, gx = x0 + p - 1;
        uint32_t sa = sb + x_off(plane, p, g);
        if (yy >= 0 && yy < HH && gx >= 0 && gx < WW) {
            CPA16(sa, xb + ((size_t)yy * WW + gx) * CIN + g * 8);
        } else {
            asm volatile("st.shared.v4.b32 [%0], {%1,%1,%1,%1};" :: "r"(sa), "r"(0u) : "memory");
        }
    }
#pragma unroll
    for (int it = 0; it < 8; it++) {
        int idx = tid + it * 256;
        int r = idx >> 4, g = idx & 15;
        CPA16(sb + a_off(0, r, g), wb + (size_t)r * CIN + g * 8);
    }
    CPA_COMMIT();                                    // G0
#pragma unroll
    for (int it = 0; it < 8; it++) {
        int idx = tid + it * 256;
        int r = idx >> 4, g = idx & 15;
        CPA16(sb + a_off(1, r, g), wb + (size_t)(COUT * CIN) + (size_t)r * CIN + g * 8);
    }
    CPA_COMMIT();                                    // G1
}

__global__ void __launch_bounds__(256, 1)
conv_mma_kernel(const __half* __restrict__ xt, float* __restrict__ out) {
    extern __shared__ __align__(1024) char smem[];
    uint32_t sb = smem_u32(smem);
    int tid = threadIdx.x, wid = tid >> 5, lane = tid & 31;
    int wo = (wid & 1) * 64;       // o base
    int wx = (wid >> 1) * 16;      // x base (0/16/32/48)

    int u = blockIdx.x;
    if (u >= NUNITS) return;

    // decode unit -> (b, y, x0)
    int b  = u >> 6;
    int rem = u & 63;
    int y  = (rem >> 1) * 4;
    int x0 = (rem & 1) * 64;
    const __half* wb = g_wA + ((size_t)b * NTAP) * COUT * CIN;
    const __half* xb = xt + ((size_t)b * HH) * WW * CIN;

    stage_unit(xb, wb, y, x0, sb, tid);   // first unit's G0, G1

    float acc[4][4][2][4];

    for (;;) {
#pragma unroll
        for (int yr = 0; yr < 4; yr++)
#pragma unroll
            for (int mt = 0; mt < 4; mt++)
#pragma unroll
                for (int nt = 0; nt < 2; nt++)
#pragma unroll
                    for (int q = 0; q < 4; q++) acc[yr][mt][nt][q] = 0.f;

        for (int t = 0; t < NTAP; t++) {
            CPA_WAIT(1);
            __syncthreads();            // one barrier per tap

            int buf = t % 3;
            int dy = t / 3, dx = t - 3 * dy;

            int ar_l = lane & 15, ac_g2 = (lane >> 4);
            int bnt = (lane >> 4) & 1, bg = (lane >> 3) & 1, br_l = lane & 7;

#pragma unroll
            for (int ks = 0; ks < 8; ks++) {
                uint32_t afr[4][4];
                uint32_t bfr[4][4];
#pragma unroll
                for (int mt = 0; mt < 4; mt++) {
                    int r = wo + mt * 16 + ar_l;
                    ldsm_x4(afr[mt], sb + a_off(buf, r, ks * 2 + ac_g2));
                }
#pragma unroll
                for (int yr = 0; yr < 4; yr++) {
                    int p = wx + bnt * 8 + br_l + dx;
                    ldsm_x4(bfr[yr], sb + x_off(dy + yr, p, ks * 2 + bg));
                }
#pragma unroll
                for (int yr = 0; yr < 4; yr++)
#pragma unroll
                    for (int mt = 0; mt < 4; mt++)
#pragma unroll
                        for (int nt = 0; nt < 2; nt++)
                            mma16816(acc[yr][mt][nt], afr[mt], &bfr[yr][nt * 2]);
            }
            // prefetch A for tap t+2 into buf (t+2)%3
            if (t + 2 < NTAP) {
                int pbuf = (t + 2) % 3;
                const __half* asrc = wb + (size_t)(t + 2) * COUT * CIN;
#pragma unroll
                for (int it = 0; it < 8; it++) {
                    int idx = tid + it * 256;
                    int r = idx >> 4, g = idx & 15;
                    CPA16(sb + a_off(pbuf, r, g), asrc + (size_t)r * CIN + g * 8);
                }
            }
            CPA_COMMIT();   // one group per tap (possibly empty)
        }

        __syncthreads();    // all warps done reading this unit's X/A smem

        // ---- issue NEXT unit's staging before this unit's epilogue ----
        int un = u + NGRID;
        bool more = (un < NUNITS);
        int nb = 0, ny = 0, nx0 = 0;
        const __half *nwb = wb, *nxb = xb;
        if (more) {
            nb  = un >> 6;
            int nrem = un & 63;
            ny  = (nrem >> 1) * 4;
            nx0 = (nrem & 1) * 64;
            nwb = g_wA + ((size_t)nb * NTAP) * COUT * CIN;
            nxb = xt + ((size_t)nb * HH) * WW * CIN;
            stage_unit(nxb, nwb, ny, nx0, sb, tid);   // flies under epilogue
        }

        // ---- epilogue: c frags -> out[b][o][y+yr][x0+x] ----
        int ml = lane >> 2, nl = (lane & 3) * 2;
#pragma unroll
        for (int yr = 0; yr < 4; yr++) {
            float* ob = out + ((size_t)b * COUT) * HH * WW + (size_t)(y + yr) * WW;
#pragma unroll
            for (int mt = 0; mt < 4; mt++) {
#pragma unroll
                for (int half = 0; half < 2; half++) {
                    int o = wo + mt * 16 + ml + half * 8;
                    float* orow = ob + (size_t)o * HH * WW;
#pragma unroll
                    for (int nt = 0; nt < 2; nt++) {
                        int xx = x0 + wx + nt * 8 + nl;
                        float2 v;
                        v.x = acc[yr][mt][nt][half * 2 + 0];
                        v.y = acc[yr][mt][nt][half * 2 + 1];
                        *(float2*)(orow + xx) = v;
                    }
                }
            }
        }

        if (!more) break;
        u = un; b = nb; y = ny; x0 = nx0; wb = nwb; xb = nxb;
    }
}

// ---------------------------------------------------------------------------
extern "C" void kernel_launch(void* const* d_in, const int* in_sizes, int n_in,
                              void* d_out, int out_size) {
    const float* x      = (const float*)d_in[0];
    const float* style  = (const float*)d_in[1];
    const float* weight = (const float*)d_in[2];
    const float* mod_w  = (const float*)d_in[3];
    const float* mod_b  = (const float*)d_in[4];
    float* out = (float*)d_out;

    modstyle_kernel<<<dim3(CIN / 4, B_), 128>>>(style, mod_w, mod_b);
    prep_kernel<<<4096, 256>>>(x, weight);

    __half* xt_ptr = nullptr;
    cudaGetSymbolAddress((void**)&xt_ptr, g_xt);
    cudaFuncSetAttribute(conv_mma_kernel, cudaFuncAttributeMaxDynamicSharedMemorySize, SM_TOTAL);
    conv_mma_kernel<<<NGRID, 256, SM_TOTAL>>>(xt_ptr, out);
}

// round 16
// speedup vs baseline: 2.1437x; 1.0025x over previous
#include <cuda_runtime.h>
#include <cuda_fp16.h>
#include <cstdint>
#include <cstddef>

#define EPS 1e-8f
#define B_   16
#define CIN  128
#define COUT 128
#define HH   128
#define WW   128
#define SS   512
#define NTAP 9

// ---------------- scratch (__device__ globals; no allocs allowed) ----------
__device__ float  g_s[B_ * CIN];
__device__ __half g_wA[(size_t)B_ * NTAP * COUT * CIN];   // [b][t][o][i]
__device__ __half g_xt[(size_t)B_ * HH * WW * CIN];       // [b][y][x][i] NHWC

// ---------------- helpers ---------------------------------------------------
__device__ __forceinline__ uint32_t smem_u32(const void* p) {
    uint32_t a;
    asm("{ .reg .u64 t; cvta.to.shared.u64 t, %1; cvt.u32.u64 %0, t; }" : "=r"(a) : "l"(p));
    return a;
}
#define CPA16(s, g) \
    asm volatile("cp.async.cg.shared.global [%0], [%1], 16;" :: "r"(s), "l"(g) : "memory")
#define CPA_COMMIT() asm volatile("cp.async.commit_group;" ::: "memory")
#define CPA_WAIT(n)  asm volatile("cp.async.wait_group %0;" :: "n"(n) : "memory")

__device__ __forceinline__ void ldsm_x4(uint32_t* r, uint32_t addr) {
    asm volatile("ldmatrix.sync.aligned.m8n8.x4.shared.b16 {%0,%1,%2,%3}, [%4];"
                 : "=r"(r[0]), "=r"(r[1]), "=r"(r[2]), "=r"(r[3]) : "r"(addr));
}
__device__ __forceinline__ void mma16816(float* c, const uint32_t* a, const uint32_t* b) {
    asm volatile(
        "mma.sync.aligned.m16n8k16.row.col.f32.f16.f16.f32 "
        "{%0,%1,%2,%3}, {%4,%5,%6,%7}, {%8,%9}, {%0,%1,%2,%3};"
        : "+f"(c[0]), "+f"(c[1]), "+f"(c[2]), "+f"(c[3])
        : "r"(a[0]), "r"(a[1]), "r"(a[2]), "r"(a[3]), "r"(b[0]), "r"(b[1]));
}

// ---------------------------------------------------------------------------
// Kernel 1: s[b][i] = style[b] . mod_w[i] + mod_b[i]  (tiny, reads mod_w once)
// ---------------------------------------------------------------------------
__global__ void modstyle_kernel(const float* __restrict__ style,
                                const float* __restrict__ mod_w,
                                const float* __restrict__ mod_b) {
    int b = blockIdx.y;
    int w = threadIdx.x >> 5, lane = threadIdx.x & 31;
    int i = blockIdx.x * 4 + w;

    const float4* mw = (const float4*)(mod_w + (size_t)i * SS);
    const float4* st = (const float4*)(style + (size_t)b * SS);
    float acc = 0.f;
#pragma unroll
    for (int j = 0; j < 4; j++) {
        float4 a = mw[lane + j * 32];
        float4 s4 = st[lane + j * 32];
        acc += a.x * s4.x + a.y * s4.y + a.z * s4.z + a.w * s4.w;
    }
#pragma unroll
    for (int off = 16; off > 0; off >>= 1)
        acc += __shfl_xor_sync(0xFFFFFFFFu, acc, off);
    if (lane == 0) g_s[b * CIN + i] = acc + mod_b[i];
}

// ---------------------------------------------------------------------------
// Kernel 2 (FUSED): blocks [0,2048) transpose NCHW->NHWC fp16;
//                   blocks [2048,4096) demod (reads g_s) -> g_wA.
// ---------------------------------------------------------------------------
#define TSTR 130
__global__ void __launch_bounds__(256)
prep_kernel(const float* __restrict__ x, const float* __restrict__ weight) {
    __shared__ __half T[WW * TSTR];     // transpose role only (33 KB)
    __shared__ float s_sm[CIN];
    __shared__ float red[256];
    int tid = threadIdx.x;

    if (blockIdx.x < 2048) {
        // ---- transpose role: blk -> (b, y) ----
        int blk = blockIdx.x;
        int b = blk >> 7, y = blk & 127;
        const float* xb = x + ((size_t)b * CIN) * HH * WW + (size_t)y * WW;
        for (int idx = tid; idx < CIN * WW; idx += 256) {
            int i = idx >> 7, xx = idx & 127;
            T[xx * TSTR + i] = __float2half_rn(xb[(size_t)i * HH * WW + xx]);
        }
        __syncthreads();
        __half* dst = g_xt + (((size_t)b * HH + y) * WW) * CIN;
        for (int idx = tid; idx < WW * (CIN / 2); idx += 256) {
            int xx = idx >> 6, ip = idx & 63;
            uint32_t v = *(const uint32_t*)&T[xx * TSTR + 2 * ip];
            *(uint32_t*)&dst[(size_t)xx * CIN + 2 * ip] = v;
        }
    } else {
        // ---- demod role: blk -> (b, o) ----
        int blk = blockIdx.x - 2048;
        int b = blk >> 7, o = blk & 127;
        if (tid < CIN) s_sm[tid] = g_s[b * CIN + tid];
        __syncthreads();

        const float* w = weight + (size_t)o * CIN * NTAP;   // w[o][i][t]
        float p = 0.f;
        for (int idx = tid; idx < CIN * NTAP; idx += 256) {
            int i = idx / NTAP, t = idx - i * NTAP;
            float v = w[i * NTAP + t] * s_sm[i];
            p += v * v;
        }
        red[tid] = p;
        __syncthreads();
        for (int off = 128; off > 0; off >>= 1) {
            if (tid < off) red[tid] += red[tid + off];
            __syncthreads();
        }
        float dec = rsqrtf(red[0] + EPS);

        if (tid < CIN) {
            int i = tid;
            float sv = s_sm[i] * dec;
#pragma unroll
            for (int t = 0; t < NTAP; t++)
                g_wA[(((size_t)b * NTAP + t) * COUT + o) * CIN + i] =
                    __float2half_rn(w[i * NTAP + t] * sv);
        }
    }
}

// ---------------------------------------------------------------------------
// Kernel 3: PERSISTENT mma.sync conv. grid = 148 CTAs, grid-stride over
// 1024 units (b, ygrp, xh). Per unit: o=128 x x=64 x 4 y-rows.
//   SPLIT COMMIT: G0 = {X planes 0..3, A0} (all tap-0 needs),
//                 G1 = {X planes 4..5, A1} (needed by tap 3 / tap 1).
//   Issue timing unchanged (all at unit boundary, under prior epilogue);
//   only the wait granularity improves: tap 0 waits on 100 KB, not 133 KB.
//   Then one commit group per tap (A[t+2] prefetch, possibly empty).
// smem = 3*32768 (A) + 6*66*256 (X) = 199680 B -> 1 CTA/SM.
// Warp tile 64(o) x 16(x) x 4 rows. Per k16: 4 ldsm_x4 A + 4 ldsm_x4 B -> 32 MMA.
// ---------------------------------------------------------------------------
#define SM_A     0
#define A_BYTES  32768
#define SM_X     (3 * A_BYTES)
#define XROWS    66
#define XPLANE   (XROWS * 256)
#define SM_TOTAL (SM_X + 6 * XPLANE)           // 98304 + 101376 = 199680
#define NUNITS   ((HH / 4) * 2 * B_)           // 1024
#define NGRID    148

__device__ __forceinline__ uint32_t a_off(int buf, int r, int g) {
    return (uint32_t)(SM_A + buf * A_BYTES + r * 256 + ((g ^ (r & 7)) << 4));
}
__device__ __forceinline__ uint32_t x_off(int plane, int p, int g) {
    return (uint32_t)(SM_X + (plane * XROWS + p) * 256 + ((g ^ (p & 7)) << 4));
}

// stage X planes [pl0, pl1) via cp.async (zero-pad halos)
__device__ __forceinline__ void stage_x_planes(const __half* __restrict__ xb,
                                               int pl0, int pl1, int y, int x0,
                                               uint32_t sb, int tid) {
    int n = (pl1 - pl0) * XROWS * 16;
    for (int idx = tid; idx < n; idx += 256) {
        int plane = pl0 + idx / (XROWS * 16);
        int rem = idx % (XROWS * 16);
        int p = rem >> 4, g = rem & 15;
        int yy = y - 1 + plane, gx = x0 + p - 1;
        uint32_t sa = sb + x_off(plane, p, g);
        if (yy >= 0 && yy < HH && gx >= 0 && gx < WW) {
            CPA16(sa, xb + ((size_t)yy * WW + gx) * CIN + g * 8);
        } else {
            asm volatile("st.shared.v4.b32 [%0], {%1,%1,%1,%1};" :: "r"(sa), "r"(0u) : "memory");
        }
    }
}

// issue one unit's staging: G0 = {planes 0..3, A0}, G1 = {planes 4..5, A1}
__device__ __forceinline__ void stage_unit(const __half* __restrict__ xb,
                                           const __half* __restrict__ wb,
                                           int y, int x0, uint32_t sb, int tid) {
    stage_x_planes(xb, 0, 4, y, x0, sb, tid);
#pragma unroll
    for (int it = 0; it < 8; it++) {
        int idx = tid + it * 256;
        int r = idx >> 4, g = idx & 15;
        CPA16(sb + a_off(0, r, g), wb + (size_t)r * CIN + g * 8);
    }
    CPA_COMMIT();                                    // G0
    stage_x_planes(xb, 4, 6, y, x0, sb, tid);
#pragma unroll
    for (int it = 0; it < 8; it++) {
        int idx = tid + it * 256;
        int r = idx >> 4, g = idx & 15;
        CPA16(sb + a_off(1, r, g), wb + (size_t)(COUT * CIN) + (size_t)r * CIN + g * 8);
    }
    CPA_COMMIT();                                    // G1
}

__global__ void __launch_bounds__(256, 1)
conv_mma_kernel(const __half* __restrict__ xt, float* __restrict__ out) {
    extern __shared__ __align__(1024) char smem[];
    uint32_t sb = smem_u32(smem);
    int tid = threadIdx.x, wid = tid >> 5, lane = tid & 31;
    int wo = (wid & 1) * 64;       // o base
    int wx = (wid >> 1) * 16;      // x base (0/16/32/48)

    int u = blockIdx.x;
    if (u >= NUNITS) return;

    // decode unit -> (b, y, x0)
    int b  = u >> 6;
    int rem = u & 63;
    int y  = (rem >> 1) * 4;
    int x0 = (rem & 1) * 64;
    const __half* wb = g_wA + ((size_t)b * NTAP) * COUT * CIN;
    const __half* xb = xt + ((size_t)b * HH) * WW * CIN;

    stage_unit(xb, wb, y, x0, sb, tid);   // first unit's G0, G1

    float acc[4][4][2][4];

    for (;;) {
#pragma unroll
        for (int yr = 0; yr < 4; yr++)
#pragma unroll
            for (int mt = 0; mt < 4; mt++)
#pragma unroll
                for (int nt = 0; nt < 2; nt++)
#pragma unroll
                    for (int q = 0; q < 4; q++) acc[yr][mt][nt][q] = 0.f;

        for (int t = 0; t < NTAP; t++) {
            CPA_WAIT(1);
            __syncthreads();            // one barrier per tap

            int buf = t % 3;
            int dy = t / 3, dx = t - 3 * dy;

            int ar_l = lane & 15, ac_g2 = (lane >> 4);
            int bnt = (lane >> 4) & 1, bg = (lane >> 3) & 1, br_l = lane & 7;

#pragma unroll
            for (int ks = 0; ks < 8; ks++) {
                uint32_t afr[4][4];
                uint32_t bfr[4][4];
#pragma unroll
                for (int mt = 0; mt < 4; mt++) {
                    int r = wo + mt * 16 + ar_l;
                    ldsm_x4(afr[mt], sb + a_off(buf, r, ks * 2 + ac_g2));
                }
#pragma unroll
                for (int yr = 0; yr < 4; yr++) {
                    int p = wx + bnt * 8 + br_l + dx;
                    ldsm_x4(bfr[yr], sb + x_off(dy + yr, p, ks * 2 + bg));
                }
#pragma unroll
                for (int yr = 0; yr < 4; yr++)
#pragma unroll
                    for (int mt = 0; mt < 4; mt++)
#pragma unroll
                        for (int nt = 0; nt < 2; nt++)
                            mma16816(acc[yr][mt][nt], afr[mt], &bfr[yr][nt * 2]);
            }
            // prefetch A for tap t+2 into buf (t+2)%3
            if (t + 2 < NTAP) {
                int pbuf = (t + 2) % 3;
                const __half* asrc = wb + (size_t)(t + 2) * COUT * CIN;
#pragma unroll
                for (int it = 0; it < 8; it++) {
                    int idx = tid + it * 256;
                    int r = idx >> 4, g = idx & 15;
                    CPA16(sb + a_off(pbuf, r, g), asrc + (size_t)r * CIN + g * 8);
                }
            }
            CPA_COMMIT();   // one group per tap (possibly empty)
        }

        __syncthreads();    // all warps done reading this unit's X/A smem

        // ---- issue NEXT unit's staging before this unit's epilogue ----
        int un = u + NGRID;
        bool more = (un < NUNITS);
        int nb = 0, ny = 0, nx0 = 0;
        const __half *nwb = wb, *nxb = xb;
        if (more) {
            nb  = un >> 6;
            int nrem = un & 63;
            ny  = (nrem >> 1) * 4;
            nx0 = (nrem & 1) * 64;
            nwb = g_wA + ((size_t)nb * NTAP) * COUT * CIN;
            nxb = xt + ((size_t)nb * HH) * WW * CIN;
            stage_unit(nxb, nwb, ny, nx0, sb, tid);   // flies under epilogue
        }

        // ---- epilogue: c frags -> out[b][o][y+yr][x0+x] ----
        int ml = lane >> 2, nl = (lane & 3) * 2;
#pragma unroll
        for (int yr = 0; yr < 4; yr++) {
            float* ob = out + ((size_t)b * COUT) * HH * WW + (size_t)(y + yr) * WW;
#pragma unroll
            for (int mt = 0; mt < 4; mt++) {
#pragma unroll
                for (int half = 0; half < 2; half++) {
                    int o = wo + mt * 16 + ml + half * 8;
                    float* orow = ob + (size_t)o * HH * WW;
#pragma unroll
                    for (int nt = 0; nt < 2; nt++) {
                        int xx = x0 + wx + nt * 8 + nl;
                        float2 v;
                        v.x = acc[yr][mt][nt][half * 2 + 0];
                        v.y = acc[yr][mt][nt][half * 2 + 1];
                        *(float2*)(orow + xx) = v;
                    }
                }
            }
        }

        if (!more) break;
        u = un; b = nb; y = ny; x0 = nx0; wb = nwb; xb = nxb;
    }
}

// ---------------------------------------------------------------------------
extern "C" void kernel_launch(void* const* d_in, const int* in_sizes, int n_in,
                              void* d_out, int out_size) {
    const float* x      = (const float*)d_in[0];
    const float* style  = (const float*)d_in[1];
    const float* weight = (const float*)d_in[2];
    const float* mod_w  = (const float*)d_in[3];
    const float* mod_b  = (const float*)d_in[4];
    float* out = (float*)d_out;

    modstyle_kernel<<<dim3(CIN / 4, B_), 128>>>(style, mod_w, mod_b);
    prep_kernel<<<4096, 256>>>(x, weight);

    __half* xt_ptr = nullptr;
    cudaGetSymbolAddress((void**)&xt_ptr, g_xt);
    cudaFuncSetAttribute(conv_mma_kernel, cudaFuncAttributeMaxDynamicSharedMemorySize, SM_TOTAL);
    conv_mma_kernel<<<NGRID, 256, SM_TOTAL>>>(xt_ptr, out);
}